// round 13
// baseline (speedup 1.0000x reference)
#include <cuda_runtime.h>
#include <math.h>

// ---------------------------------------------------------------------------
// Problem constants
// ---------------------------------------------------------------------------
#define B_       32
#define Q_       300
#define C_       91
#define A_       10
#define TOPK_    50
#define NKEEP_   256
#define ML_      128          // MASK_LEN
#define LMAX_    23           // zigzag first 256 coeffs all have k,l <= 22
#define TOT_     (Q_ * C_)    // 27300
#define NCH_     8
#define CHUNK_   3413         // ceil(27300/8)
#define CAP_EQ   5000
#define CAP_EX   512

// Output layout (flattened tuple, f32)
#define OFF_S   ((size_t)0)
#define OFF_L   ((size_t)(B_ * TOPK_))                         // 1600
#define OFF_B   (OFF_L + (size_t)(B_ * TOPK_))                 // 3200
#define OFF_M   (OFF_B + (size_t)(B_ * TOPK_ * 4))             // 9600
#define OFF_SI  (OFF_M + (size_t)(B_ * TOPK_ * ML_ * ML_))     // 26224000
#define OFF_LI  (OFF_SI + (size_t)(B_ * TOPK_))                // 26225600
#define OFF_LA  (OFF_LI + (size_t)(B_ * TOPK_))                // 26227200

// ---------------------------------------------------------------------------
// Device scratch (no allocations allowed)
// ---------------------------------------------------------------------------
__device__ float    g_D[LMAX_ * ML_];    // first 23 rows of the DCT matrix
__device__ int      g_topq[B_ * TOPK_];  // final topk query indices
__device__ unsigned g_hist[B_ * 256];    // level-0 histograms (zeroed by topk_kernel)

// Monotonic float->uint mapping (larger float => larger uint)
__device__ __forceinline__ unsigned mono(float f) {
    unsigned b = __float_as_uint(f);
    return (b & 0x80000000u) ? ~b : (b | 0x80000000u);
}

// Parallel suffix-scan bin selection over hist[0..255] (hist[256] must be 0).
// Destroys hist. Exactly one thread updates s_prefix / s_krem.
__device__ __forceinline__ void select_bin(unsigned* hist, int tid, int shift,
                                           unsigned* s_prefix, int* s_krem)
{
    for (int off = 1; off < 256; off <<= 1) {
        unsigned v = 0;
        if (tid < 256 && tid + off < 256) v = hist[tid + off];
        __syncthreads();
        if (tid < 256) hist[tid] += v;
        __syncthreads();
    }
    int krem = *s_krem;
    __syncthreads();
    if (tid < 256) {
        int sb  = (int)hist[tid];
        int sb1 = (tid == 255) ? 0 : (int)hist[tid + 1];
        if (sb >= krem && sb1 < krem) {
            *s_prefix |= ((unsigned)tid) << shift;
            *s_krem    = krem - sb1;
        }
    }
    __syncthreads();
}

// ---------------------------------------------------------------------------
// Kernel A: per-(batch,chunk) level-0 histogram -> g_hist, + DCT table gen.
// grid = 256 CTAs (32 batches x 8 chunks), 256 threads.
// ---------------------------------------------------------------------------
__global__ void __launch_bounds__(256) hist_kernel(const float* __restrict__ logits)
{
    int bid = blockIdx.x;
    int b   = bid >> 3;
    int ch  = bid & 7;
    int tid = threadIdx.x;

    // DCT table: 2944 entries over 256 CTAs = 12 each (guarded)
    if (tid < 12) {
        int idx = bid * 12 + tid;
        if (idx < LMAX_ * ML_) {
            const double s2n = sqrt(2.0 / (double)ML_);
            int k = idx / ML_, m = idx % ML_;
            double v = cospi((2.0 * m + 1.0) * k / (2.0 * ML_)) * s2n;
            if (k == 0) v *= sqrt(0.5);
            g_D[idx] = (float)v;
        }
    }

    __shared__ unsigned h[256];
    h[tid] = 0;
    __syncthreads();

    int start = ch * CHUNK_;
    int end   = start + CHUNK_ < TOT_ ? start + CHUNK_ : TOT_;
    const float* base = logits + (size_t)b * TOT_;
    for (int i = start + tid; i < end; i += 256)
        atomicAdd(&h[mono(__ldg(base + i)) >> 24], 1u);
    __syncthreads();

    if (h[tid]) atomicAdd(&g_hist[b * 256 + tid], h[tid]);
}

// ---------------------------------------------------------------------------
// Kernel B: per-batch select. ONE gmem scan (L2-hot): compacts >bin0 directly
// into the selection list (guaranteed <50) and ==bin0 into the refine list.
// Then 3 refine levels on the SMEM list, rank sort, epilogue.
// Zeroes g_hist[b] for the next graph replay.
// ---------------------------------------------------------------------------
__global__ void __launch_bounds__(1024) topk_kernel(
    const float* __restrict__ logits, const float* __restrict__ bbox,
    const float* __restrict__ interms, const float* __restrict__ actions,
    const int* __restrict__ tsz, float* __restrict__ out)
{
    int b   = blockIdx.x;
    int tid = threadIdx.x;
    const float* base = logits + (size_t)b * TOT_;

    __shared__ unsigned hist[257];
    __shared__ unsigned eq_u[CAP_EQ];
    __shared__ int      eq_i[CAP_EQ];
    __shared__ int      eqex[CAP_EX];
    __shared__ unsigned sel_u[TOPK_];
    __shared__ int      sel_idx[TOPK_];
    __shared__ float    fin_v[TOPK_];
    __shared__ int      fin_i[TOPK_];
    __shared__ unsigned s_prefix;
    __shared__ int      s_krem, s_neq, s_cntgt, s_cnte;

    if (tid == 0) { s_prefix = 0; s_krem = TOPK_; s_neq = 0; s_cntgt = 0; s_cnte = 0; }
    if (tid < 256) hist[tid] = g_hist[b * 256 + tid];
    if (tid == 256) hist[256] = 0;
    __syncthreads();
    if (tid < 256) g_hist[b * 256 + tid] = 0;   // reset for next replay
    select_bin(hist, tid, 24, &s_prefix, &s_krem);

    unsigned bin0 = s_prefix >> 24;

    // ---- single scan: byte>bin0 -> sel (count < 50); byte==bin0 -> eq list ----
    for (int i = tid; i < TOT_; i += 1024) {
        unsigned u = mono(__ldg(base + i));
        unsigned byte = u >> 24;
        if (byte > bin0) {
            int s = atomicAdd(&s_cntgt, 1);
            sel_u[s] = u; sel_idx[s] = i;
        } else if (byte == bin0) {
            int s = atomicAdd(&s_neq, 1);
            if (s < CAP_EQ) { eq_u[s] = u; eq_i[s] = i; }
        }
    }
    __syncthreads();
    bool ovf = (s_neq > CAP_EQ);
    int  neq = s_neq < CAP_EQ ? s_neq : CAP_EQ;

    // ---- levels 1..3: refine on SMEM list (or gmem if overflow) ----
    for (int lev = 1; lev < 4; lev++) {
        int shift = 24 - 8 * lev;
        if (tid < 257) hist[tid] = 0;
        __syncthreads();
        unsigned pref    = s_prefix;
        unsigned hi_mask = 0xffffffffu << (shift + 8);
        if (!ovf) {
            for (int i = tid; i < neq; i += 1024) {
                unsigned u = eq_u[i];
                if ((u & hi_mask) == (pref & hi_mask))
                    atomicAdd(&hist[(u >> shift) & 0xff], 1u);
            }
        } else {
            for (int i = tid; i < TOT_; i += 1024) {
                unsigned u = mono(__ldg(base + i));
                if ((u & hi_mask) == (pref & hi_mask))
                    atomicAdd(&hist[(u >> shift) & 0xff], 1u);
            }
        }
        __syncthreads();
        select_bin(hist, tid, shift, &s_prefix, &s_krem);
    }

    unsigned uthr    = s_prefix;
    int      need_eq = s_krem;          // slots filled by u == uthr (index order)
    int      cnt_gt  = TOPK_ - need_eq; // count of u > uthr (guaranteed < 50)

    // ---- gather remaining strictly-greater (same top byte, u > uthr) ----
    if (!ovf) {
        for (int i = tid; i < neq; i += 1024) {
            unsigned u = eq_u[i];
            if (u > uthr) {
                int s = atomicAdd(&s_cntgt, 1);
                sel_u[s] = u; sel_idx[s] = eq_i[i];
            }
        }
    } else {
        for (int i = tid; i < TOT_; i += 1024) {
            unsigned u = mono(__ldg(base + i));
            if ((u >> 24) == bin0 && u > uthr) {
                int s = atomicAdd(&s_cntgt, 1);
                sel_u[s] = u; sel_idx[s] = i;
            }
        }
    }

    // ---- equal-to-pivot fill, index-ascending ----
    bool fell_back = ovf;
    if (!ovf) {
        for (int i = tid; i < neq; i += 1024) {
            if (eq_u[i] == uthr) {
                int s = atomicAdd(&s_cnte, 1);
                if (s < CAP_EX) eqex[s] = eq_i[i];
            }
        }
        __syncthreads();
        if (s_cnte <= CAP_EX) {
            if (tid == 0) {
                int cnt = s_cnte, last = -1;
                for (int r = 0; r < need_eq; r++) {
                    int best = 0x7fffffff;
                    for (int j = 0; j < cnt; j++) {
                        int v = eqex[j];
                        if (v > last && v < best) best = v;
                    }
                    sel_u[cnt_gt + r]   = uthr;
                    sel_idx[cnt_gt + r] = best;
                    last = best;
                }
            }
        } else {
            fell_back = true;
        }
        __syncthreads();
    }
    if (fell_back) {
        // Rare path: thread 0 rebuilds equal-set fill from gmem in index order.
        if (tid == 0) {
            int p = 0;
            for (int i = 0; i < TOT_ && p < need_eq; i++) {
                if (mono(__ldg(base + i)) == uthr) {
                    sel_u[cnt_gt + p]   = uthr;
                    sel_idx[cnt_gt + p] = i;
                    p++;
                }
            }
        }
        __syncthreads();
    }
    __syncthreads();

    // ---- O(50^2) rank sort: (value desc, index asc) ----
    if (tid < TOPK_) {
        unsigned ui = sel_u[tid]; int ii = sel_idx[tid];
        int r = 0;
        for (int j = 0; j < TOPK_; j++) {
            unsigned uj = sel_u[j]; int ij = sel_idx[j];
            if (uj > ui || (uj == ui && ij < ii)) r++;
        }
        unsigned fb = (ui & 0x80000000u) ? (ui ^ 0x80000000u) : ~ui;
        fin_v[r] = __uint_as_float(fb);
        fin_i[r] = ii;
    }
    __syncthreads();

    // ---- epilogue: all small outputs ----
    if (tid < TOPK_) {
        int r   = tid;
        float val = fin_v[r];
        int   gi  = fin_i[r];
        int   q   = gi / C_;
        int   lab = gi - q * C_;
        g_topq[b * TOPK_ + r] = q;

        out[OFF_S + b * TOPK_ + r] = 1.0f / (1.0f + expf(-val));
        out[OFF_L + b * TOPK_ + r] = (float)lab;

        const float* bb = bbox + ((size_t)b * Q_ + q) * 4;
        float cx = bb[0], cy = bb[1], w = bb[2], h = bb[3];
        float ihh = (float)tsz[b * 2 + 0];
        float iww = (float)tsz[b * 2 + 1];
        float* ob = out + OFF_B + ((size_t)b * TOPK_ + r) * 4;
        ob[0] = (cx - 0.5f * w) * iww;
        ob[1] = (cy - 0.5f * h) * ihh;
        ob[2] = (cx + 0.5f * w) * iww;
        ob[3] = (cy + 0.5f * h) * ihh;

        const float* it = interms + ((size_t)b * Q_ + q) * C_;
        float m = it[0]; int am = 0;
        for (int c = 1; c < C_; c++) {
            float v = it[c];
            if (v > m) { m = v; am = c; }
        }
        out[OFF_SI + b * TOPK_ + r] = 1.0f / (1.0f + expf(-m));
        out[OFF_LI + b * TOPK_ + r] = (float)am;
    }
    if (tid == 0) {
        const float* ac = actions + (size_t)b * A_;
        float m = ac[0]; int am = 0;
        for (int a = 1; a < A_; a++)
            if (ac[a] > m) { m = ac[a]; am = a; }
        out[OFF_LA + b] = (float)am;
    }
}

// ---------------------------------------------------------------------------
// Masks kernel: one CTA per (b, rank) tile. 512 threads, 2 CTAs/SM (32 warps).
// Phase 0: gather Z[l][k] = sv[zigzag(k,l)] (closed form).
// Phase 1: T[l][n] = sum_k Z[l][k] D[k][n], k-parity mirror over left half.
// Phase 2: l-parity mirror outer product; thread owns 8 rows x 2 left cols
//   (32 accumulators). Per l-pair: 4 bcast float4 T + 2 float2 D + 32 FMA.
// ---------------------------------------------------------------------------
__global__ void __launch_bounds__(512, 2) masks_kernel(
    const float* __restrict__ vec, float* __restrict__ out)
{
    __shared__ float sD[LMAX_ * ML_];     // 11.75 KB
    __shared__ float sT[LMAX_ * ML_];     // 11.75 KB
    __shared__ float sv[NKEEP_];          // 1 KB
    __shared__ float sZ[LMAX_ * 24];      // 23x23 padded to stride 24
    __shared__ float red[33];

    int tid  = threadIdx.x;
    int tile = blockIdx.x;
    int b    = tile / TOPK_;
    int q    = g_topq[tile];

    if (tid < NKEEP_) sv[tid] = vec[((size_t)b * Q_ + q) * NKEEP_ + tid];
    {   // vectorized D load: 2944 floats = 736 float4
        const float4* src = reinterpret_cast<const float4*>(g_D);
        float4*       dst = reinterpret_cast<float4*>(sD);
        for (int i = tid; i < (LMAX_ * ML_) / 4; i += 512) dst[i] = src[i];
    }
    __syncthreads();

    // Phase 0: gather Z (needs sv ready)
    for (int idx = tid; idx < LMAX_ * LMAX_; idx += 512) {
        int l = idx / LMAX_, k = idx - l * LMAX_;
        int s = k + l;
        float v = 0.0f;
        if (s <= 21 || (s == 22 && l <= 2)) {
            int c = ((s * (s + 1)) >> 1) + ((s & 1) ? k : l);
            v = sv[c];
        }
        sZ[l * 24 + k] = v;
    }
    __syncthreads();

    // Phase 1: T[l][n] via dense Z, k-parity mirror split. 368 units.
    if (tid < LMAX_ * 16) {
        int l  = tid >> 4;
        int n0 = (tid & 15) << 2;
        float te0 = 0, te1 = 0, te2 = 0, te3 = 0;
        float to0 = 0, to1 = 0, to2 = 0, to3 = 0;
        const float* pd = &sD[n0];
        const float* pz = &sZ[l * 24];
        #pragma unroll 1
        for (int kp = 0; kp < 11; kp++) {
            float4 de = *reinterpret_cast<const float4*>(pd);        // k even
            float4 dq = *reinterpret_cast<const float4*>(pd + ML_);  // k odd
            float  ze = pz[0];
            float  zo = pz[1];
            te0 = fmaf(ze, de.x, te0); te1 = fmaf(ze, de.y, te1);
            te2 = fmaf(ze, de.z, te2); te3 = fmaf(ze, de.w, te3);
            to0 = fmaf(zo, dq.x, to0); to1 = fmaf(zo, dq.y, to1);
            to2 = fmaf(zo, dq.z, to2); to3 = fmaf(zo, dq.w, to3);
            pd += 2 * ML_;
            pz += 2;
        }
        {   // k = 22 (even)
            float4 de = *reinterpret_cast<const float4*>(pd);
            float  ze = pz[0];
            te0 = fmaf(ze, de.x, te0); te1 = fmaf(ze, de.y, te1);
            te2 = fmaf(ze, de.z, te2); te3 = fmaf(ze, de.w, te3);
        }
        float4 wl, wr;
        wl.x = te0 + to0; wl.y = te1 + to1; wl.z = te2 + to2; wl.w = te3 + to3;
        wr.x = te3 - to3; wr.y = te2 - to2; wr.z = te1 - to1; wr.w = te0 - to0;
        *reinterpret_cast<float4*>(&sT[l * ML_ + n0]) = wl;
        *reinterpret_cast<float4*>(&sT[l * ML_ + 124 - n0]) = wr;
    }
    __syncthreads();

    // Phase 2: l-parity mirror outer product over left half
    int warp = tid >> 5;        // 0..15
    int lane = tid & 31;
    int n0   = warp << 3;       // 8 rows per warp
    int m0   = lane << 1;       // left cols m0, m0+1 (0..63)

    float E[8][2], O[8][2];
    #pragma unroll
    for (int i = 0; i < 8; i++) {
        E[i][0] = 0.0f; E[i][1] = 0.0f;
        O[i][0] = 0.0f; O[i][1] = 0.0f;
    }

    const float* pD = &sD[m0];
    const float* pT = &sT[n0];
    // 23 = 11*2 + 1: (even,odd) pairs, then final even row l=22
    #pragma unroll 1
    for (int lp = 0; lp < 11; lp++) {
        float2 de = *reinterpret_cast<const float2*>(pD);          // l even
        float2 dc = *reinterpret_cast<const float2*>(pD + ML_);    // l odd
        float4 e0 = *reinterpret_cast<const float4*>(pT);
        float4 e1 = *reinterpret_cast<const float4*>(pT + 4);
        float4 o0 = *reinterpret_cast<const float4*>(pT + ML_);
        float4 o1 = *reinterpret_cast<const float4*>(pT + ML_ + 4);
        float te[8] = {e0.x,e0.y,e0.z,e0.w, e1.x,e1.y,e1.z,e1.w};
        float to[8] = {o0.x,o0.y,o0.z,o0.w, o1.x,o1.y,o1.z,o1.w};
        #pragma unroll
        for (int i = 0; i < 8; i++) {
            E[i][0] = fmaf(te[i], de.x, E[i][0]);
            E[i][1] = fmaf(te[i], de.y, E[i][1]);
            O[i][0] = fmaf(to[i], dc.x, O[i][0]);
            O[i][1] = fmaf(to[i], dc.y, O[i][1]);
        }
        pD += 2 * ML_;
        pT += 2 * ML_;
    }
    {   // l = 22 (even)
        float2 de = *reinterpret_cast<const float2*>(pD);
        float4 e0 = *reinterpret_cast<const float4*>(pT);
        float4 e1 = *reinterpret_cast<const float4*>(pT + 4);
        float te[8] = {e0.x,e0.y,e0.z,e0.w, e1.x,e1.y,e1.z,e1.w};
        #pragma unroll
        for (int i = 0; i < 8; i++) {
            E[i][0] = fmaf(te[i], de.x, E[i][0]);
            E[i][1] = fmaf(te[i], de.y, E[i][1]);
        }
    }

    // combine in place: E <- left value (E+O), O <- right value (E-O)
    float mx = -3.402823466e38f, mn = 3.402823466e38f;
    #pragma unroll
    for (int i = 0; i < 8; i++)
        #pragma unroll
        for (int j = 0; j < 2; j++) {
            float s = E[i][j] + O[i][j];
            float d = E[i][j] - O[i][j];
            E[i][j] = s; O[i][j] = d;
            mx = fmaxf(mx, fmaxf(s, d));
            mn = fminf(mn, fminf(s, d));
        }
    for (int o = 16; o; o >>= 1) {
        mx = fmaxf(mx, __shfl_xor_sync(0xffffffffu, mx, o));
        mn = fminf(mn, __shfl_xor_sync(0xffffffffu, mn, o));
    }
    if (lane == 0) { red[warp] = mx; red[16 + warp] = mn; }
    __syncthreads();
    if (tid == 0) {
        float MX = red[0], MN = red[16];
        for (int w = 1; w < 16; w++) { MX = fmaxf(MX, red[w]); MN = fminf(MN, red[16 + w]); }
        red[32] = 0.5f * (MX + MN);
    }
    __syncthreads();
    float th = red[32];

    // write: left pair at col m0, mirrored pair at col 126-m0
    float* ob = out + OFF_M + (size_t)tile * (ML_ * ML_);
    #pragma unroll
    for (int i = 0; i < 8; i++) {
        float* row = ob + (size_t)(n0 + i) * ML_;
        float2 wl, wr;
        wl.x = E[i][0] > th ? 1.0f : 0.0f;       // col m0
        wl.y = E[i][1] > th ? 1.0f : 0.0f;       // col m0+1
        wr.x = O[i][1] > th ? 1.0f : 0.0f;       // col 126-m0
        wr.y = O[i][0] > th ? 1.0f : 0.0f;       // col 127-m0
        *reinterpret_cast<float2*>(row + m0) = wl;
        *reinterpret_cast<float2*>(row + 126 - m0) = wr;
    }
}

// ---------------------------------------------------------------------------
// Launch
// ---------------------------------------------------------------------------
extern "C" void kernel_launch(void* const* d_in, const int* in_sizes, int n_in,
                              void* d_out, int out_size)
{
    const float* logits  = (const float*)d_in[0];
    const float* bbox    = (const float*)d_in[1];
    const float* vec     = (const float*)d_in[2];
    const float* interms = (const float*)d_in[3];
    const float* actions = (const float*)d_in[4];
    const int*   tsz     = (const int*)d_in[5];
    float* out = (float*)d_out;

    hist_kernel<<<B_ * NCH_, 256>>>(logits);
    topk_kernel<<<B_, 1024>>>(logits, bbox, interms, actions, tsz, out);
    masks_kernel<<<B_ * TOPK_, 512>>>(vec, out);
}

// round 14
// speedup vs baseline: 1.1310x; 1.1310x over previous
#include <cuda_runtime.h>
#include <math.h>

// ---------------------------------------------------------------------------
// Problem constants
// ---------------------------------------------------------------------------
#define B_       32
#define Q_       300
#define C_       91
#define A_       10
#define TOPK_    50
#define NKEEP_   256
#define ML_      128          // MASK_LEN
#define LMAX_    23           // zigzag first 256 coeffs all have k,l <= 22
#define TOT_     (Q_ * C_)    // 27300
#define NF4_     6825         // TOT_ / 4 (exact)
#define CAP_EQ   5000
#define CAP_EX   512

// Output layout (flattened tuple, f32)
#define OFF_S   ((size_t)0)
#define OFF_L   ((size_t)(B_ * TOPK_))                         // 1600
#define OFF_B   (OFF_L + (size_t)(B_ * TOPK_))                 // 3200
#define OFF_M   (OFF_B + (size_t)(B_ * TOPK_ * 4))             // 9600
#define OFF_SI  (OFF_M + (size_t)(B_ * TOPK_ * ML_ * ML_))     // 26224000
#define OFF_LI  (OFF_SI + (size_t)(B_ * TOPK_))                // 26225600
#define OFF_LA  (OFF_LI + (size_t)(B_ * TOPK_))                // 26227200

// ---------------------------------------------------------------------------
// Device scratch (no allocations allowed)
// ---------------------------------------------------------------------------
__device__ float g_D[LMAX_ * ML_];          // first 23 rows of the DCT matrix
__device__ int   g_topq[B_ * TOPK_];        // final topk query indices

// Monotonic float->uint mapping (larger float => larger uint)
__device__ __forceinline__ unsigned mono(float f) {
    unsigned b = __float_as_uint(f);
    return (b & 0x80000000u) ? ~b : (b | 0x80000000u);
}

// Parallel suffix-scan bin selection over hist[0..255] (hist[256] must be 0).
// Destroys hist. Exactly one thread updates s_prefix / s_krem.
__device__ __forceinline__ void select_bin(unsigned* hist, int tid, int shift,
                                           unsigned* s_prefix, int* s_krem)
{
    for (int off = 1; off < 256; off <<= 1) {
        unsigned v = 0;
        if (tid < 256 && tid + off < 256) v = hist[tid + off];
        __syncthreads();
        if (tid < 256) hist[tid] += v;
        __syncthreads();
    }
    int krem = *s_krem;
    __syncthreads();
    if (tid < 256) {
        int sb  = (int)hist[tid];
        int sb1 = (tid == 255) ? 0 : (int)hist[tid + 1];
        if (sb >= krem && sb1 < krem) {
            *s_prefix |= ((unsigned)tid) << shift;
            *s_krem    = krem - sb1;
        }
    }
    __syncthreads();
}

// ---------------------------------------------------------------------------
// Top-50 via radix select; values register-resident after ONE vectorized
// gmem pass (7x LDG.128/thread, atomics decoupled from loads).
// Also writes this CTA's DCT slice.
// ---------------------------------------------------------------------------
__global__ void __launch_bounds__(1024) topk_kernel(
    const float* __restrict__ logits, const float* __restrict__ bbox,
    const float* __restrict__ interms, const float* __restrict__ actions,
    const int* __restrict__ tsz, float* __restrict__ out)
{
    int b   = blockIdx.x;
    int tid = threadIdx.x;
    const float* base = logits + (size_t)b * TOT_;
    const float4* base4 = reinterpret_cast<const float4*>(base);

    __shared__ unsigned hist[257];
    __shared__ unsigned eq_u[CAP_EQ];
    __shared__ int      eq_i[CAP_EQ];
    __shared__ int      eqex[CAP_EX];
    __shared__ unsigned sel_u[TOPK_];
    __shared__ int      sel_idx[TOPK_];
    __shared__ float    fin_v[TOPK_];
    __shared__ int      fin_i[TOPK_];
    __shared__ unsigned s_prefix;
    __shared__ int      s_krem, s_neq, s_cntgt, s_cnte;

    // ---- DCT table slice: 2944 entries / 32 CTAs = 92 each ----
    {
        const double s2n = sqrt(2.0 / (double)ML_);
        const double s05 = sqrt(0.5);
        int idx0 = b * 92;
        for (int j = tid; j < 92; j += 1024) {
            int idx = idx0 + j;
            int k = idx / ML_, m = idx % ML_;
            double v = cospi((2.0 * m + 1.0) * k / (2.0 * ML_)) * s2n;
            if (k == 0) v *= s05;
            g_D[idx] = (float)v;
        }
    }

    if (tid == 0) { s_prefix = 0; s_krem = TOPK_; s_neq = 0; s_cntgt = 0; s_cnte = 0; }
    if (tid < 257) hist[tid] = 0;
    __syncthreads();

    // ---- vectorized load: 7 independent LDG.128 per thread ----
    unsigned uv[28];
    #pragma unroll
    for (int p = 0; p < 7; p++) {
        int j = tid + p * 1024;
        if (j < NF4_) {
            float4 v = __ldg(base4 + j);
            uv[4 * p + 0] = mono(v.x);
            uv[4 * p + 1] = mono(v.y);
            uv[4 * p + 2] = mono(v.z);
            uv[4 * p + 3] = mono(v.w);
        } else {
            uv[4 * p + 0] = 0; uv[4 * p + 1] = 0;
            uv[4 * p + 2] = 0; uv[4 * p + 3] = 0;
        }
    }

    // ---- level-0 histogram from registers ----
    #pragma unroll
    for (int p = 0; p < 7; p++) {
        int j = tid + p * 1024;
        if (j < NF4_) {
            atomicAdd(&hist[uv[4 * p + 0] >> 24], 1u);
            atomicAdd(&hist[uv[4 * p + 1] >> 24], 1u);
            atomicAdd(&hist[uv[4 * p + 2] >> 24], 1u);
            atomicAdd(&hist[uv[4 * p + 3] >> 24], 1u);
        }
    }
    __syncthreads();
    select_bin(hist, tid, 24, &s_prefix, &s_krem);

    // ---- compact candidates sharing top byte of pivot (registers) ----
    unsigned bin0 = s_prefix >> 24;
    #pragma unroll
    for (int p = 0; p < 7; p++) {
        int j = tid + p * 1024;
        if (j < NF4_) {
            #pragma unroll
            for (int c = 0; c < 4; c++) {
                unsigned u = uv[4 * p + c];
                if ((u >> 24) == bin0) {
                    int s = atomicAdd(&s_neq, 1);
                    if (s < CAP_EQ) { eq_u[s] = u; eq_i[s] = 4 * j + c; }
                }
            }
        }
    }
    __syncthreads();
    bool ovf = (s_neq > CAP_EQ);
    int  neq = s_neq < CAP_EQ ? s_neq : CAP_EQ;

    // ---- levels 1..3: refine on SMEM list (or registers if overflow) ----
    for (int lev = 1; lev < 4; lev++) {
        int shift = 24 - 8 * lev;
        if (tid < 257) hist[tid] = 0;
        __syncthreads();
        unsigned pref    = s_prefix;
        unsigned hi_mask = 0xffffffffu << (shift + 8);
        if (!ovf) {
            for (int i = tid; i < neq; i += 1024) {
                unsigned u = eq_u[i];
                if ((u & hi_mask) == (pref & hi_mask))
                    atomicAdd(&hist[(u >> shift) & 0xff], 1u);
            }
        } else {
            #pragma unroll
            for (int p = 0; p < 7; p++) {
                int j = tid + p * 1024;
                if (j < NF4_) {
                    #pragma unroll
                    for (int c = 0; c < 4; c++) {
                        unsigned u = uv[4 * p + c];
                        if ((u & hi_mask) == (pref & hi_mask))
                            atomicAdd(&hist[(u >> shift) & 0xff], 1u);
                    }
                }
            }
        }
        __syncthreads();
        select_bin(hist, tid, shift, &s_prefix, &s_krem);
    }

    unsigned uthr    = s_prefix;
    int      need_eq = s_krem;          // slots filled by u == uthr (index order)
    int      cnt_gt  = TOPK_ - need_eq; // count of u > uthr (guaranteed < 50)

    // ---- gather strictly-greater (registers) ----
    #pragma unroll
    for (int p = 0; p < 7; p++) {
        int j = tid + p * 1024;
        if (j < NF4_) {
            #pragma unroll
            for (int c = 0; c < 4; c++) {
                unsigned u = uv[4 * p + c];
                if (u > uthr) {
                    int s = atomicAdd(&s_cntgt, 1);
                    sel_u[s] = u; sel_idx[s] = 4 * j + c;
                }
            }
        }
    }

    // ---- equal-to-pivot fill, index-ascending ----
    bool fell_back = ovf;
    if (!ovf) {
        for (int i = tid; i < neq; i += 1024) {
            if (eq_u[i] == uthr) {
                int s = atomicAdd(&s_cnte, 1);
                if (s < CAP_EX) eqex[s] = eq_i[i];
            }
        }
        __syncthreads();
        if (s_cnte <= CAP_EX) {
            if (tid == 0) {
                int cnt = s_cnte, last = -1;
                for (int r = 0; r < need_eq; r++) {
                    int best = 0x7fffffff;
                    for (int j = 0; j < cnt; j++) {
                        int v = eqex[j];
                        if (v > last && v < best) best = v;
                    }
                    sel_u[cnt_gt + r]   = uthr;
                    sel_idx[cnt_gt + r] = best;
                    last = best;
                }
            }
        } else {
            fell_back = true;
        }
        __syncthreads();
    }
    if (fell_back) {
        // Rare path: thread 0 rebuilds equal-set fill from gmem in index order.
        if (tid == 0) {
            int p = 0;
            for (int i = 0; i < TOT_ && p < need_eq; i++) {
                if (mono(__ldg(base + i)) == uthr) {
                    sel_u[cnt_gt + p]   = uthr;
                    sel_idx[cnt_gt + p] = i;
                    p++;
                }
            }
        }
        __syncthreads();
    }
    __syncthreads();

    // ---- O(50^2) rank sort: (value desc, index asc) ----
    if (tid < TOPK_) {
        unsigned ui = sel_u[tid]; int ii = sel_idx[tid];
        int r = 0;
        for (int j = 0; j < TOPK_; j++) {
            unsigned uj = sel_u[j]; int ij = sel_idx[j];
            if (uj > ui || (uj == ui && ij < ii)) r++;
        }
        unsigned fb = (ui & 0x80000000u) ? (ui ^ 0x80000000u) : ~ui;
        fin_v[r] = __uint_as_float(fb);
        fin_i[r] = ii;
    }
    __syncthreads();

    // ---- epilogue: all small outputs ----
    if (tid < TOPK_) {
        int r   = tid;
        float val = fin_v[r];
        int   gi  = fin_i[r];
        int   q   = gi / C_;
        int   lab = gi - q * C_;
        g_topq[b * TOPK_ + r] = q;

        out[OFF_S + b * TOPK_ + r] = 1.0f / (1.0f + expf(-val));
        out[OFF_L + b * TOPK_ + r] = (float)lab;

        const float* bb = bbox + ((size_t)b * Q_ + q) * 4;
        float cx = bb[0], cy = bb[1], w = bb[2], h = bb[3];
        float ihh = (float)tsz[b * 2 + 0];
        float iww = (float)tsz[b * 2 + 1];
        float* ob = out + OFF_B + ((size_t)b * TOPK_ + r) * 4;
        ob[0] = (cx - 0.5f * w) * iww;
        ob[1] = (cy - 0.5f * h) * ihh;
        ob[2] = (cx + 0.5f * w) * iww;
        ob[3] = (cy + 0.5f * h) * ihh;

        const float* it = interms + ((size_t)b * Q_ + q) * C_;
        float m = it[0]; int am = 0;
        for (int c = 1; c < C_; c++) {
            float v = it[c];
            if (v > m) { m = v; am = c; }
        }
        out[OFF_SI + b * TOPK_ + r] = 1.0f / (1.0f + expf(-m));
        out[OFF_LI + b * TOPK_ + r] = (float)am;
    }
    if (tid == 0) {
        const float* ac = actions + (size_t)b * A_;
        float m = ac[0]; int am = 0;
        for (int a = 1; a < A_; a++)
            if (ac[a] > m) { m = ac[a]; am = a; }
        out[OFF_LA + b] = (float)am;
    }
}

// ---------------------------------------------------------------------------
// Masks kernel: one CTA per (b, rank) tile.  (Proven R10 version, 43.6us.)
// Phase 0: gather Z[l][k] = sv[zigzag(k,l)] into SMEM (zeros elsewhere).
// Phase 1: T[l][n] = sum_k Z[l][k] D[k][n], k-parity mirror over left half.
// Phase 2: l-parity mirror outer product; thread owns 16 rows x 2 left cols.
// ---------------------------------------------------------------------------
__global__ void __launch_bounds__(256, 2) masks_kernel(
    const float* __restrict__ vec, float* __restrict__ out)
{
    __shared__ float sD[LMAX_ * ML_];     // 11.75 KB
    __shared__ float sT[LMAX_ * ML_];     // 11.75 KB
    __shared__ float sv[NKEEP_];          // 1 KB
    __shared__ float sZ[LMAX_ * 24];      // 23x23 padded to stride 24
    __shared__ float red[17];

    int tid  = threadIdx.x;
    int tile = blockIdx.x;
    int b    = tile / TOPK_;
    int q    = g_topq[tile];

    sv[tid] = vec[((size_t)b * Q_ + q) * NKEEP_ + tid];
    {   // vectorized D load: 2944 floats = 736 float4
        const float4* src = reinterpret_cast<const float4*>(g_D);
        float4*       dst = reinterpret_cast<float4*>(sD);
        for (int i = tid; i < (LMAX_ * ML_) / 4; i += 256) dst[i] = src[i];
    }
    __syncthreads();

    // Phase 0: gather Z (needs sv ready)
    for (int idx = tid; idx < LMAX_ * LMAX_; idx += 256) {
        int l = idx / LMAX_, k = idx - l * LMAX_;
        int s = k + l;
        float v = 0.0f;
        if (s <= 21 || (s == 22 && l <= 2)) {
            int c = ((s * (s + 1)) >> 1) + ((s & 1) ? k : l);
            v = sv[c];
        }
        sZ[l * 24 + k] = v;
    }
    __syncthreads();

    // Phase 1: T[l][n] via dense Z, k-parity mirror split. 368 units.
    for (int u = tid; u < LMAX_ * 16; u += 256) {
        int l  = u >> 4;
        int n0 = (u & 15) << 2;
        float te0 = 0, te1 = 0, te2 = 0, te3 = 0;
        float to0 = 0, to1 = 0, to2 = 0, to3 = 0;
        const float* pd = &sD[n0];
        const float* pz = &sZ[l * 24];
        #pragma unroll 1
        for (int kp = 0; kp < 11; kp++) {
            float4 de = *reinterpret_cast<const float4*>(pd);        // k even
            float4 dq = *reinterpret_cast<const float4*>(pd + ML_);  // k odd
            float  ze = pz[0];
            float  zo = pz[1];
            te0 = fmaf(ze, de.x, te0); te1 = fmaf(ze, de.y, te1);
            te2 = fmaf(ze, de.z, te2); te3 = fmaf(ze, de.w, te3);
            to0 = fmaf(zo, dq.x, to0); to1 = fmaf(zo, dq.y, to1);
            to2 = fmaf(zo, dq.z, to2); to3 = fmaf(zo, dq.w, to3);
            pd += 2 * ML_;
            pz += 2;
        }
        {   // k = 22 (even)
            float4 de = *reinterpret_cast<const float4*>(pd);
            float  ze = pz[0];
            te0 = fmaf(ze, de.x, te0); te1 = fmaf(ze, de.y, te1);
            te2 = fmaf(ze, de.z, te2); te3 = fmaf(ze, de.w, te3);
        }
        float4 wl, wr;
        wl.x = te0 + to0; wl.y = te1 + to1; wl.z = te2 + to2; wl.w = te3 + to3;
        // right block at cols 124-n0 .. 127-n0 (reversed component order)
        wr.x = te3 - to3; wr.y = te2 - to2; wr.z = te1 - to1; wr.w = te0 - to0;
        *reinterpret_cast<float4*>(&sT[l * ML_ + n0]) = wl;
        *reinterpret_cast<float4*>(&sT[l * ML_ + 124 - n0]) = wr;
    }
    __syncthreads();

    // Phase 2: l-parity mirror outer product over left half
    int warp = tid >> 5;
    int lane = tid & 31;
    int n0   = warp << 4;       // 16 rows per warp
    int m0   = lane << 1;       // left cols m0, m0+1 (0..63)

    float E[16][2], O[16][2];
    #pragma unroll
    for (int i = 0; i < 16; i++) {
        E[i][0] = 0.0f; E[i][1] = 0.0f;
        O[i][0] = 0.0f; O[i][1] = 0.0f;
    }

    const float* pD = &sD[m0];
    const float* pT = &sT[n0];
    // 23 = 11*2 + 1: handle (even,odd) pairs, then final even row l=22
    #pragma unroll 1
    for (int lp = 0; lp < 11; lp++) {
        float2 de = *reinterpret_cast<const float2*>(pD);          // l even
        float2 dc = *reinterpret_cast<const float2*>(pD + ML_);    // l odd
        float4 e0 = *reinterpret_cast<const float4*>(pT);
        float4 e1 = *reinterpret_cast<const float4*>(pT + 4);
        float4 e2 = *reinterpret_cast<const float4*>(pT + 8);
        float4 e3 = *reinterpret_cast<const float4*>(pT + 12);
        float4 o0 = *reinterpret_cast<const float4*>(pT + ML_);
        float4 o1 = *reinterpret_cast<const float4*>(pT + ML_ + 4);
        float4 o2 = *reinterpret_cast<const float4*>(pT + ML_ + 8);
        float4 o3 = *reinterpret_cast<const float4*>(pT + ML_ + 12);
        float te[16] = {e0.x,e0.y,e0.z,e0.w, e1.x,e1.y,e1.z,e1.w,
                        e2.x,e2.y,e2.z,e2.w, e3.x,e3.y,e3.z,e3.w};
        float to[16] = {o0.x,o0.y,o0.z,o0.w, o1.x,o1.y,o1.z,o1.w,
                        o2.x,o2.y,o2.z,o2.w, o3.x,o3.y,o3.z,o3.w};
        #pragma unroll
        for (int i = 0; i < 16; i++) {
            E[i][0] = fmaf(te[i], de.x, E[i][0]);
            E[i][1] = fmaf(te[i], de.y, E[i][1]);
            O[i][0] = fmaf(to[i], dc.x, O[i][0]);
            O[i][1] = fmaf(to[i], dc.y, O[i][1]);
        }
        pD += 2 * ML_;
        pT += 2 * ML_;
    }
    {   // l = 22 (even)
        float2 de = *reinterpret_cast<const float2*>(pD);
        float4 e0 = *reinterpret_cast<const float4*>(pT);
        float4 e1 = *reinterpret_cast<const float4*>(pT + 4);
        float4 e2 = *reinterpret_cast<const float4*>(pT + 8);
        float4 e3 = *reinterpret_cast<const float4*>(pT + 12);
        float te[16] = {e0.x,e0.y,e0.z,e0.w, e1.x,e1.y,e1.z,e1.w,
                        e2.x,e2.y,e2.z,e2.w, e3.x,e3.y,e3.z,e3.w};
        #pragma unroll
        for (int i = 0; i < 16; i++) {
            E[i][0] = fmaf(te[i], de.x, E[i][0]);
            E[i][1] = fmaf(te[i], de.y, E[i][1]);
        }
    }

    // combine in place: E <- left value (E+O), O <- right value (E-O)
    float mx = -3.402823466e38f, mn = 3.402823466e38f;
    #pragma unroll
    for (int i = 0; i < 16; i++)
        #pragma unroll
        for (int j = 0; j < 2; j++) {
            float s = E[i][j] + O[i][j];
            float d = E[i][j] - O[i][j];
            E[i][j] = s; O[i][j] = d;
            mx = fmaxf(mx, fmaxf(s, d));
            mn = fminf(mn, fminf(s, d));
        }
    for (int o = 16; o; o >>= 1) {
        mx = fmaxf(mx, __shfl_xor_sync(0xffffffffu, mx, o));
        mn = fminf(mn, __shfl_xor_sync(0xffffffffu, mn, o));
    }
    if (lane == 0) { red[warp] = mx; red[8 + warp] = mn; }
    __syncthreads();
    if (tid == 0) {
        float MX = red[0], MN = red[8];
        for (int w = 1; w < 8; w++) { MX = fmaxf(MX, red[w]); MN = fminf(MN, red[8 + w]); }
        red[16] = 0.5f * (MX + MN);
    }
    __syncthreads();
    float th = red[16];

    // write: left pair at col m0, mirrored pair at col 126-m0
    float* ob = out + OFF_M + (size_t)tile * (ML_ * ML_);
    #pragma unroll
    for (int i = 0; i < 16; i++) {
        float* row = ob + (size_t)(n0 + i) * ML_;
        float2 wl, wr;
        wl.x = E[i][0] > th ? 1.0f : 0.0f;       // col m0
        wl.y = E[i][1] > th ? 1.0f : 0.0f;       // col m0+1
        wr.x = O[i][1] > th ? 1.0f : 0.0f;       // col 126-m0 = 127-(m0+1)
        wr.y = O[i][0] > th ? 1.0f : 0.0f;       // col 127-m0
        *reinterpret_cast<float2*>(row + m0) = wl;
        *reinterpret_cast<float2*>(row + 126 - m0) = wr;
    }
}

// ---------------------------------------------------------------------------
// Launch
// ---------------------------------------------------------------------------
extern "C" void kernel_launch(void* const* d_in, const int* in_sizes, int n_in,
                              void* d_out, int out_size)
{
    const float* logits  = (const float*)d_in[0];
    const float* bbox    = (const float*)d_in[1];
    const float* vec     = (const float*)d_in[2];
    const float* interms = (const float*)d_in[3];
    const float* actions = (const float*)d_in[4];
    const int*   tsz     = (const int*)d_in[5];
    float* out = (float*)d_out;

    topk_kernel<<<B_, 1024>>>(logits, bbox, interms, actions, tsz, out);
    masks_kernel<<<B_ * TOPK_, 256>>>(vec, out);
}